// round 15
// baseline (speedup 1.0000x reference)
#include <cuda_runtime.h>

using ull = unsigned long long;

#define R 3

// ---------------- f32x2 packed-math helpers (Blackwell FFMA2 path) ----------------

__device__ __forceinline__ ull ffma2(ull a, ull b, ull c) {
    ull d;
    asm("fma.rn.f32x2 %0, %1, %2, %3;" : "=l"(d) : "l"(a), "l"(b), "l"(c));
    return d;
}
__device__ __forceinline__ ull pk2(float x, float y) {
    ull r;
    asm("mov.b64 %0, {%1, %2};" : "=l"(r) : "f"(x), "f"(y));
    return r;
}
__device__ __forceinline__ void unpk2(ull v, float& x, float& y) {
    asm("mov.b64 {%0, %1}, %2;" : "=f"(x), "=f"(y) : "l"(v));
}
// packed ReLU via paired FMNMX (halves are independent regs; pack/unpack elided)
__device__ __forceinline__ ull relu2(ull v) {
    float a, b;
    unpk2(v, a, b);
    return pk2(fmaxf(a, 0.f), fmaxf(b, 0.f));
}
__device__ __forceinline__ float hadd2(ull v) {
    float a, b;
    unpk2(v, a, b);
    return a + b;
}
__device__ __forceinline__ float tanh_fast(float x) {
    float y;
    asm("tanh.approx.f32 %0, %1;" : "=f"(y) : "f"(x));
    return y;
}

// ---------------- constant-memory weight cache (all but W2) ----------------
struct __align__(16) CParams {
    float W1[4 * 64];      // 256
    float B1[64];
    float B2[32];
    float Wf[96];          // folded enc3*proj, column-major: Wf[o*32 + j]
    float Pbp[16];         // {beff0,0, beff1,0, beff2,0, 0...}
    float FhX0[10 * 32];
    float FhX1[10 * 16];
    float Fbh[10 * 32];
    float FoMu2[10 * 32];
    float FoAl2[10 * 32];
    float FoMu1[10 * 16];
    float FoAl1[10 * 16];
    float FbA[10 * 8];     // {bmu1,0, ba1,0, bmu2,0, ba2,0}
    float Fb0[32];         // [2l]=bmu0, [2l+1]=exp(-tanh(ba0))
};

__constant__ CParams cP;
__device__ CParams g_stage;

// ---------------- bake kernel: fold/permute weights into g_stage (1 block, 128 thr) ----------------
__global__ void bake_kernel(const float* __restrict__ enc_w1, const float* __restrict__ enc_b1,
                            const float* __restrict__ enc_b2,
                            const float* __restrict__ enc_w3, const float* __restrict__ enc_b3,
                            const float* __restrict__ proj_w, const float* __restrict__ proj_b,
                            const float* __restrict__ flow_wh, const float* __restrict__ flow_bh,
                            const float* __restrict__ flow_wmu, const float* __restrict__ flow_bmu,
                            const float* __restrict__ flow_wa, const float* __restrict__ flow_ba) {
    const int tid = threadIdx.x;
    for (int i = tid; i < 4 * 64; i += 128)  g_stage.W1[i] = enc_w1[i];
    for (int i = tid; i < 64;     i += 128)  g_stage.B1[i] = enc_b1[i];
    for (int i = tid; i < 32;     i += 128)  g_stage.B2[i] = enc_b2[i];
    if (tid < 96) {
        int j = tid / 3, o = tid % 3;
        float s = 0.f;
#pragma unroll
        for (int k = 0; k < 8; k++) s += enc_w3[j * 8 + k] * proj_w[k * 3 + o];
        g_stage.Wf[o * 32 + j] = s;
    }
    if (tid < 8) {
        float s = 0.f;
        if (tid < 3) {
            s = proj_b[tid];
#pragma unroll
            for (int k = 0; k < 8; k++) s += enc_b3[k] * proj_w[k * 3 + tid];
        }
        g_stage.Pbp[2 * tid]     = s;
        g_stage.Pbp[2 * tid + 1] = 0.f;
    }
    // flow bake with unit permutation (n<16: u=2n+1 deg-2; n>=16: u=2(n-16) deg-1)
    for (int i = tid; i < 10 * 16; i += 128) {
        int l = i >> 4, n = i & 15;
        int uo = 2 * n + 1, ue = 2 * n;
        const float* wh = flow_wh + l * 96;
        g_stage.FhX0[l * 32 + n]      = wh[uo];
        g_stage.FhX0[l * 32 + 16 + n] = wh[ue];
        g_stage.FhX1[l * 16 + n]      = wh[32 + uo];
        g_stage.Fbh[l * 32 + n]       = flow_bh[l * 32 + uo];
        g_stage.Fbh[l * 32 + 16 + n]  = flow_bh[l * 32 + ue];
        g_stage.FoMu2[l * 32 + n]      = flow_wmu[l * 96 + uo * 3 + 2];
        g_stage.FoMu2[l * 32 + 16 + n] = flow_wmu[l * 96 + ue * 3 + 2];
        g_stage.FoAl2[l * 32 + n]      = flow_wa[l * 96 + uo * 3 + 2];
        g_stage.FoAl2[l * 32 + 16 + n] = flow_wa[l * 96 + ue * 3 + 2];
        g_stage.FoMu1[l * 16 + n] = flow_wmu[l * 96 + ue * 3 + 1];
        g_stage.FoAl1[l * 16 + n] = flow_wa[l * 96 + ue * 3 + 1];
    }
    if (tid < 10) {
        int l = tid;
        g_stage.FbA[l * 8 + 0] = flow_bmu[l * 3 + 1]; g_stage.FbA[l * 8 + 1] = 0.f;
        g_stage.FbA[l * 8 + 2] = flow_ba [l * 3 + 1]; g_stage.FbA[l * 8 + 3] = 0.f;
        g_stage.FbA[l * 8 + 4] = flow_bmu[l * 3 + 2]; g_stage.FbA[l * 8 + 5] = 0.f;
        g_stage.FbA[l * 8 + 6] = flow_ba [l * 3 + 2]; g_stage.FbA[l * 8 + 7] = 0.f;
        g_stage.Fb0[2 * l]     = flow_bmu[l * 3 + 0];
        g_stage.Fb0[2 * l + 1] = expf(-tanhf(flow_ba[l * 3 + 0]));
    }
}

// ---------------- main kernel: W2 via direct LDG (L1-resident), rest via const/LDC ----------------

__global__ __launch_bounds__(128, 4)
void gsi_kernel(const float* __restrict__ states, const float* __restrict__ enc_w2,
                float* __restrict__ out, int B) {
    const int tid = threadIdx.x;
    const int rbase = blockIdx.x * (128 * R) + tid;

    ull xp[R][4];
#pragma unroll
    for (int q = 0; q < R; q++) {
        int rl = rbase + q * 128;
        if (rl > B - 1) rl = B - 1;                      // clamp load; store guarded later
        float4 sv = reinterpret_cast<const float4*>(states)[rl];
        xp[q][0] = pk2(sv.x, sv.x); xp[q][1] = pk2(sv.y, sv.y);
        xp[q][2] = pk2(sv.z, sv.z); xp[q][3] = pk2(sv.w, sv.w);
    }

    // ---- fused enc1 (4->64) + enc2 (64->32), single pass, h1 chunked by 8 ----
    ull h2[R][16];
    {
        const ulonglong2* pb = reinterpret_cast<const ulonglong2*>(cP.B2);
#pragma unroll
        for (int p = 0; p < 8; p++) {
            ulonglong2 v = pb[p];
#pragma unroll
            for (int q = 0; q < R; q++) { h2[q][2 * p] = v.x; h2[q][2 * p + 1] = v.y; }
        }
    }
#pragma unroll 1
    for (int c = 0; c < 8; c++) {
        ull h1[R][4];
        const ulonglong2* pb1 = reinterpret_cast<const ulonglong2*>(cP.B1 + c * 8);
#pragma unroll
        for (int p = 0; p < 2; p++) {
            ulonglong2 v = pb1[p];
#pragma unroll
            for (int q = 0; q < R; q++) { h1[q][2 * p] = v.x; h1[q][2 * p + 1] = v.y; }
        }
#pragma unroll
        for (int i = 0; i < 4; i++) {
            const ulonglong2* w = reinterpret_cast<const ulonglong2*>(cP.W1 + i * 64 + c * 8);
#pragma unroll
            for (int p = 0; p < 2; p++) {
                ulonglong2 v = w[p];
#pragma unroll
                for (int q = 0; q < R; q++) {
                    h1[q][2 * p]     = ffma2(xp[q][i], v.x, h1[q][2 * p]);
                    h1[q][2 * p + 1] = ffma2(xp[q][i], v.y, h1[q][2 * p + 1]);
                }
            }
        }
#pragma unroll
        for (int j = 0; j < 4; j++) {
            ull ab[R], bb[R];
#pragma unroll
            for (int q = 0; q < R; q++) {
                float a, b;
                unpk2(h1[q][j], a, b);
                a = fmaxf(a, 0.f); b = fmaxf(b, 0.f);
                ab[q] = pk2(a, a); bb[q] = pk2(b, b);
            }
            const int u = c * 8 + 2 * j;
            // W2 rows via LDG (warp-uniform address -> broadcast; L1-resident 8KB)
            const ulonglong2* wa = reinterpret_cast<const ulonglong2*>(enc_w2 + u * 32);
            const ulonglong2* wb = reinterpret_cast<const ulonglong2*>(enc_w2 + u * 32 + 32);
#pragma unroll
            for (int p = 0; p < 8; p++) {
                ulonglong2 v = wa[p];
#pragma unroll
                for (int q = 0; q < R; q++) {
                    h2[q][2 * p]     = ffma2(ab[q], v.x, h2[q][2 * p]);
                    h2[q][2 * p + 1] = ffma2(ab[q], v.y, h2[q][2 * p + 1]);
                }
            }
#pragma unroll
            for (int p = 0; p < 8; p++) {
                ulonglong2 v = wb[p];
#pragma unroll
                for (int q = 0; q < R; q++) {
                    h2[q][2 * p]     = ffma2(bb[q], v.x, h2[q][2 * p]);
                    h2[q][2 * p + 1] = ffma2(bb[q], v.y, h2[q][2 * p + 1]);
                }
            }
        }
    }

    // ---- folded enc3+proj: 32 -> 3, dot-form ----
    float x0[R], x1[R], x2[R];
    {
        ull ax0[R], ax1[R], ax2[R];
        {
            const ulonglong2* pb = reinterpret_cast<const ulonglong2*>(cP.Pbp);
            ulonglong2 v0 = pb[0];
            ull v2 = reinterpret_cast<const ull*>(cP.Pbp)[2];
#pragma unroll
            for (int q = 0; q < R; q++) { ax0[q] = v0.x; ax1[q] = v0.y; ax2[q] = v2; }
        }
        const ull* w0p = reinterpret_cast<const ull*>(cP.Wf);
        const ull* w1p = reinterpret_cast<const ull*>(cP.Wf + 32);
        const ull* w2p = reinterpret_cast<const ull*>(cP.Wf + 64);
#pragma unroll
        for (int j = 0; j < 16; j++) {
            ull w0 = w0p[j], w1 = w1p[j], w2 = w2p[j];
#pragma unroll
            for (int q = 0; q < R; q++) {
                ull h = relu2(h2[q][j]);
                ax0[q] = ffma2(h, w0, ax0[q]);
                ax1[q] = ffma2(h, w1, ax1[q]);
                ax2[q] = ffma2(h, w2, ax2[q]);
            }
        }
#pragma unroll
        for (int q = 0; q < R; q++) {
            x0[q] = hadd2(ax0[q]); x1[q] = hadd2(ax1[q]); x2[q] = hadd2(ax2[q]);
        }
    }

    // ---- MAF flow: 10 layers; output stage dot-form ----
#pragma unroll 1
    for (int l = 0; l < 10; l++) {
        const float* fhx0 = cP.FhX0 + l * 32;
        const float* fhx1 = cP.FhX1 + l * 16;
        const float* fbh  = cP.Fbh  + l * 32;
        const ull* fmu2   = reinterpret_cast<const ull*>(cP.FoMu2 + l * 32);
        const ull* fal2   = reinterpret_cast<const ull*>(cP.FoAl2 + l * 32);
        const ull* fmu1   = reinterpret_cast<const ull*>(cP.FoMu1 + l * 16);
        const ull* fal1   = reinterpret_cast<const ull*>(cP.FoAl1 + l * 16);
        const float* fba  = cP.FbA + l * 8;
        const float* fb0  = cP.Fb0 + l * 2;

        ull x0b[R], x1b[R];
#pragma unroll
        for (int q = 0; q < R; q++) { x0b[q] = pk2(x0[q], x0[q]); x1b[q] = pk2(x1[q], x1[q]); }

        ull am1[R], aa1[R], am2[R], aa2[R];
        {
            const ulonglong2* pb = reinterpret_cast<const ulonglong2*>(fba);
            ulonglong2 v0 = pb[0], v1 = pb[1];
#pragma unroll
            for (int q = 0; q < R; q++) { am1[q] = v0.x; aa1[q] = v0.y; am2[q] = v1.x; aa2[q] = v1.y; }
        }

        // ---- block1: 16 deg-2 units (x0 + x1 inputs; feed mu2/al2 only) ----
        {
            ull hh[R][8];
            const ulonglong2* pbh = reinterpret_cast<const ulonglong2*>(fbh);
#pragma unroll
            for (int p = 0; p < 4; p++) {
                ulonglong2 v = pbh[p];
#pragma unroll
                for (int q = 0; q < R; q++) { hh[q][2 * p] = v.x; hh[q][2 * p + 1] = v.y; }
            }
            const ulonglong2* w0 = reinterpret_cast<const ulonglong2*>(fhx0);
            const ulonglong2* w1 = reinterpret_cast<const ulonglong2*>(fhx1);
#pragma unroll
            for (int p = 0; p < 4; p++) {
                ulonglong2 v = w0[p];
#pragma unroll
                for (int q = 0; q < R; q++) {
                    hh[q][2 * p]     = ffma2(x0b[q], v.x, hh[q][2 * p]);
                    hh[q][2 * p + 1] = ffma2(x0b[q], v.y, hh[q][2 * p + 1]);
                }
            }
#pragma unroll
            for (int p = 0; p < 4; p++) {
                ulonglong2 v = w1[p];
#pragma unroll
                for (int q = 0; q < R; q++) {
                    hh[q][2 * p]     = ffma2(x1b[q], v.x, hh[q][2 * p]);
                    hh[q][2 * p + 1] = ffma2(x1b[q], v.y, hh[q][2 * p + 1]);
                }
            }
#pragma unroll
            for (int p = 0; p < 8; p++) {
                ull wm2 = fmu2[p], wa2 = fal2[p];
#pragma unroll
                for (int q = 0; q < R; q++) {
                    ull h = relu2(hh[q][p]);
                    am2[q] = ffma2(h, wm2, am2[q]);
                    aa2[q] = ffma2(h, wa2, aa2[q]);
                }
            }
        }
        // ---- block2: 16 deg-1 units (x0 only; feed mu1/al1 AND mu2/al2) ----
        {
            ull hh[R][8];
            const ulonglong2* pbh = reinterpret_cast<const ulonglong2*>(fbh + 16);
#pragma unroll
            for (int p = 0; p < 4; p++) {
                ulonglong2 v = pbh[p];
#pragma unroll
                for (int q = 0; q < R; q++) { hh[q][2 * p] = v.x; hh[q][2 * p + 1] = v.y; }
            }
            const ulonglong2* w0 = reinterpret_cast<const ulonglong2*>(fhx0 + 16);
#pragma unroll
            for (int p = 0; p < 4; p++) {
                ulonglong2 v = w0[p];
#pragma unroll
                for (int q = 0; q < R; q++) {
                    hh[q][2 * p]     = ffma2(x0b[q], v.x, hh[q][2 * p]);
                    hh[q][2 * p + 1] = ffma2(x0b[q], v.y, hh[q][2 * p + 1]);
                }
            }
#pragma unroll
            for (int p = 0; p < 8; p++) {
                ull wm2 = fmu2[8 + p], wa2 = fal2[8 + p];
                ull wm1 = fmu1[p],     wa1 = fal1[p];
#pragma unroll
                for (int q = 0; q < R; q++) {
                    ull h = relu2(hh[q][p]);
                    am2[q] = ffma2(h, wm2, am2[q]);
                    aa2[q] = ffma2(h, wa2, aa2[q]);
                    am1[q] = ffma2(h, wm1, am1[q]);
                    aa1[q] = ffma2(h, wa1, aa1[q]);
                }
            }
        }

        float bmu0 = fb0[0], esc0 = fb0[1];
#pragma unroll
        for (int q = 0; q < R; q++) {
            float mu1 = hadd2(am1[q]), al1 = hadd2(aa1[q]);
            float mu2 = hadd2(am2[q]), al2 = hadd2(aa2[q]);
            float t1 = tanh_fast(al1);
            float t2 = tanh_fast(al2);
            float nx0 = (x0[q] - bmu0) * esc0;
            float nx1 = (x1[q] - mu1) * __expf(-t1);
            float nx2 = (x2[q] - mu2) * __expf(-t2);
            x0[q] = nx2; x1[q] = nx1; x2[q] = nx0;
        }
    }

    // ---- squash + HSV + store  (sigmoid(x) = 0.5*(1+tanh(x/2))) ----
#pragma unroll
    for (int q = 0; q < R; q++) {
        int rq = rbase + q * 128;
        if (rq < B) {
            float t0 = tanh_fast(0.5f * x0[q]);
            float t1 = tanh_fast(0.5f * x1[q]);
            float t2 = tanh_fast(0.5f * x2[q]);
            out[3 * rq + 0] = fmaf(3.14159265358979323846f, t0, 3.14159265358979323846f);
            out[3 * rq + 1] = fmaf(0.5f, t1, 0.5f);
            out[3 * rq + 2] = fmaf(0.5f, t2, 0.5f);
        }
    }
}

extern "C" void kernel_launch(void* const* d_in, const int* in_sizes, int n_in,
                              void* d_out, int out_size) {
    (void)n_in; (void)out_size;
    const float* states   = (const float*)d_in[0];
    const float* enc_w1   = (const float*)d_in[1];
    const float* enc_b1   = (const float*)d_in[2];
    const float* enc_w2   = (const float*)d_in[3];
    const float* enc_b2   = (const float*)d_in[4];
    const float* enc_w3   = (const float*)d_in[5];
    const float* enc_b3   = (const float*)d_in[6];
    const float* proj_w   = (const float*)d_in[7];
    const float* proj_b   = (const float*)d_in[8];
    const float* flow_wh  = (const float*)d_in[9];
    const float* flow_bh  = (const float*)d_in[10];
    const float* flow_wmu = (const float*)d_in[11];
    const float* flow_bmu = (const float*)d_in[12];
    const float* flow_wa  = (const float*)d_in[13];
    const float* flow_ba  = (const float*)d_in[14];

    // 1) bake folded/permuted weights (all but W2) into device staging
    bake_kernel<<<1, 128>>>(enc_w1, enc_b1, enc_b2, enc_w3, enc_b3,
                            proj_w, proj_b, flow_wh, flow_bh, flow_wmu, flow_bmu,
                            flow_wa, flow_ba);
    // 2) staging -> __constant__ (D2D async; graph-capturable, no allocation)
    void* stage_ptr = nullptr;
    cudaGetSymbolAddress(&stage_ptr, g_stage);
    cudaMemcpyToSymbolAsync(cP, stage_ptr, sizeof(CParams), 0,
                            cudaMemcpyDeviceToDevice, 0);
    // 3) main kernel: W2 via direct LDG (L1-cached), rest via const/LDC
    const int B = in_sizes[0] / 4;
    const int grid = (B + 128 * R - 1) / (128 * R);
    gsi_kernel<<<grid, 128>>>(states, enc_w2, (float*)d_out, B);
}

// round 16
// speedup vs baseline: 1.3487x; 1.3487x over previous
#include <cuda_runtime.h>

using ull = unsigned long long;

#define R 3

// ---------------- f32x2 packed-math helpers (Blackwell FFMA2 path) ----------------

__device__ __forceinline__ ull ffma2(ull a, ull b, ull c) {
    ull d;
    asm("fma.rn.f32x2 %0, %1, %2, %3;" : "=l"(d) : "l"(a), "l"(b), "l"(c));
    return d;
}
__device__ __forceinline__ ull pk2(float x, float y) {
    ull r;
    asm("mov.b64 %0, {%1, %2};" : "=l"(r) : "f"(x), "f"(y));
    return r;
}
__device__ __forceinline__ void unpk2(ull v, float& x, float& y) {
    asm("mov.b64 {%0, %1}, %2;" : "=f"(x), "=f"(y) : "l"(v));
}
__device__ __forceinline__ ull relu2(ull v) {
    float a, b;
    unpk2(v, a, b);
    return pk2(fmaxf(a, 0.f), fmaxf(b, 0.f));
}
__device__ __forceinline__ float hadd2(ull v) {
    float a, b;
    unpk2(v, a, b);
    return a + b;
}
__device__ __forceinline__ float tanh_fast(float x) {
    float y;
    asm("tanh.approx.f32 %0, %1;" : "=f"(y) : "f"(x));
    return y;
}

// ---------------- constant-memory weight cache (warp-uniform -> LDCU/UR path) ----------------
struct __align__(16) CParams {
    float W1[4 * 64];      // 256
    float B1[64];
    float W2[64 * 32];     // 2048
    float B2[32];
    float Wf[96];          // folded enc3*proj, column-major: Wf[o*32 + j]
    float Pbp[16];         // {beff0,0, beff1,0, beff2,0, 0...}
    float FhX0[10 * 32];
    float FhX1[10 * 16];
    float Fbh[10 * 32];
    float FoMu2[10 * 32];
    float FoAl2[10 * 32];
    float FoMu1[10 * 16];
    float FoAl1[10 * 16];
    float FbA[10 * 8];     // {bmu1,0, ba1,0, bmu2,0, ba2,0}
    float Fb0[32];         // [2l]=bmu0, [2l+1]=exp(-tanh(ba0))
};

__constant__ CParams cP;
__device__ CParams g_stage;

// ---------------- bake kernel: fold/permute weights into g_stage (1 block, 128 thr) ----------------
__global__ void bake_kernel(const float* __restrict__ enc_w1, const float* __restrict__ enc_b1,
                            const float* __restrict__ enc_w2, const float* __restrict__ enc_b2,
                            const float* __restrict__ enc_w3, const float* __restrict__ enc_b3,
                            const float* __restrict__ proj_w, const float* __restrict__ proj_b,
                            const float* __restrict__ flow_wh, const float* __restrict__ flow_bh,
                            const float* __restrict__ flow_wmu, const float* __restrict__ flow_bmu,
                            const float* __restrict__ flow_wa, const float* __restrict__ flow_ba) {
    const int tid = threadIdx.x;
    for (int i = tid; i < 4 * 64; i += 128)  g_stage.W1[i] = enc_w1[i];
    for (int i = tid; i < 64;     i += 128)  g_stage.B1[i] = enc_b1[i];
    for (int i = tid; i < 64 * 32; i += 128) g_stage.W2[i] = enc_w2[i];
    for (int i = tid; i < 32;     i += 128)  g_stage.B2[i] = enc_b2[i];
    if (tid < 96) {
        int j = tid / 3, o = tid % 3;
        float s = 0.f;
#pragma unroll
        for (int k = 0; k < 8; k++) s += enc_w3[j * 8 + k] * proj_w[k * 3 + o];
        g_stage.Wf[o * 32 + j] = s;
    }
    if (tid < 8) {
        float s = 0.f;
        if (tid < 3) {
            s = proj_b[tid];
#pragma unroll
            for (int k = 0; k < 8; k++) s += enc_b3[k] * proj_w[k * 3 + tid];
        }
        g_stage.Pbp[2 * tid]     = s;
        g_stage.Pbp[2 * tid + 1] = 0.f;
    }
    // flow bake with unit permutation (n<16: u=2n+1 deg-2; n>=16: u=2(n-16) deg-1)
    for (int i = tid; i < 10 * 16; i += 128) {
        int l = i >> 4, n = i & 15;
        int uo = 2 * n + 1, ue = 2 * n;
        const float* wh = flow_wh + l * 96;
        g_stage.FhX0[l * 32 + n]      = wh[uo];
        g_stage.FhX0[l * 32 + 16 + n] = wh[ue];
        g_stage.FhX1[l * 16 + n]      = wh[32 + uo];
        g_stage.Fbh[l * 32 + n]       = flow_bh[l * 32 + uo];
        g_stage.Fbh[l * 32 + 16 + n]  = flow_bh[l * 32 + ue];
        g_stage.FoMu2[l * 32 + n]      = flow_wmu[l * 96 + uo * 3 + 2];
        g_stage.FoMu2[l * 32 + 16 + n] = flow_wmu[l * 96 + ue * 3 + 2];
        g_stage.FoAl2[l * 32 + n]      = flow_wa[l * 96 + uo * 3 + 2];
        g_stage.FoAl2[l * 32 + 16 + n] = flow_wa[l * 96 + ue * 3 + 2];
        g_stage.FoMu1[l * 16 + n] = flow_wmu[l * 96 + ue * 3 + 1];
        g_stage.FoAl1[l * 16 + n] = flow_wa[l * 96 + ue * 3 + 1];
    }
    if (tid < 10) {
        int l = tid;
        g_stage.FbA[l * 8 + 0] = flow_bmu[l * 3 + 1]; g_stage.FbA[l * 8 + 1] = 0.f;
        g_stage.FbA[l * 8 + 2] = flow_ba [l * 3 + 1]; g_stage.FbA[l * 8 + 3] = 0.f;
        g_stage.FbA[l * 8 + 4] = flow_bmu[l * 3 + 2]; g_stage.FbA[l * 8 + 5] = 0.f;
        g_stage.FbA[l * 8 + 6] = flow_ba [l * 3 + 2]; g_stage.FbA[l * 8 + 7] = 0.f;
        g_stage.Fb0[2 * l]     = flow_bmu[l * 3 + 0];
        g_stage.Fb0[2 * l + 1] = expf(-tanhf(flow_ba[l * 3 + 0]));
    }
}

// ---------------- main kernel: const-space weights, R=3, 4 blocks/SM ----------------

__global__ __launch_bounds__(128, 4)
void gsi_kernel(const float* __restrict__ states, float* __restrict__ out, int B) {
    const int tid = threadIdx.x;
    const int rbase = blockIdx.x * (128 * R) + tid;

    ull xp[R][4];
#pragma unroll
    for (int q = 0; q < R; q++) {
        int rl = rbase + q * 128;
        if (rl > B - 1) rl = B - 1;                      // clamp load; store guarded later
        float4 sv = reinterpret_cast<const float4*>(states)[rl];
        xp[q][0] = pk2(sv.x, sv.x); xp[q][1] = pk2(sv.y, sv.y);
        xp[q][2] = pk2(sv.z, sv.z); xp[q][3] = pk2(sv.w, sv.w);
    }

    // ---- fused enc1 (4->64) + enc2 (64->32), single pass, h1 chunked by 8 ----
    ull h2[R][16];
    {
        const ulonglong2* pb = reinterpret_cast<const ulonglong2*>(cP.B2);
#pragma unroll
        for (int p = 0; p < 8; p++) {
            ulonglong2 v = pb[p];
#pragma unroll
            for (int q = 0; q < R; q++) { h2[q][2 * p] = v.x; h2[q][2 * p + 1] = v.y; }
        }
    }
#pragma unroll 1
    for (int c = 0; c < 8; c++) {
        ull h1[R][4];
        const ulonglong2* pb1 = reinterpret_cast<const ulonglong2*>(cP.B1 + c * 8);
#pragma unroll
        for (int p = 0; p < 2; p++) {
            ulonglong2 v = pb1[p];
#pragma unroll
            for (int q = 0; q < R; q++) { h1[q][2 * p] = v.x; h1[q][2 * p + 1] = v.y; }
        }
#pragma unroll
        for (int i = 0; i < 4; i++) {
            const ulonglong2* w = reinterpret_cast<const ulonglong2*>(cP.W1 + i * 64 + c * 8);
#pragma unroll
            for (int p = 0; p < 2; p++) {
                ulonglong2 v = w[p];
#pragma unroll
                for (int q = 0; q < R; q++) {
                    h1[q][2 * p]     = ffma2(xp[q][i], v.x, h1[q][2 * p]);
                    h1[q][2 * p + 1] = ffma2(xp[q][i], v.y, h1[q][2 * p + 1]);
                }
            }
        }
#pragma unroll
        for (int j = 0; j < 4; j++) {
            ull ab[R], bb[R];
#pragma unroll
            for (int q = 0; q < R; q++) {
                float a, b;
                unpk2(h1[q][j], a, b);
                a = fmaxf(a, 0.f); b = fmaxf(b, 0.f);
                ab[q] = pk2(a, a); bb[q] = pk2(b, b);
            }
            const int u = c * 8 + 2 * j;
            const ulonglong2* wa = reinterpret_cast<const ulonglong2*>(cP.W2 + u * 32);
            const ulonglong2* wb = reinterpret_cast<const ulonglong2*>(cP.W2 + u * 32 + 32);
#pragma unroll
            for (int p = 0; p < 8; p++) {
                ulonglong2 v = wa[p];
#pragma unroll
                for (int q = 0; q < R; q++) {
                    h2[q][2 * p]     = ffma2(ab[q], v.x, h2[q][2 * p]);
                    h2[q][2 * p + 1] = ffma2(ab[q], v.y, h2[q][2 * p + 1]);
                }
            }
#pragma unroll
            for (int p = 0; p < 8; p++) {
                ulonglong2 v = wb[p];
#pragma unroll
                for (int q = 0; q < R; q++) {
                    h2[q][2 * p]     = ffma2(bb[q], v.x, h2[q][2 * p]);
                    h2[q][2 * p + 1] = ffma2(bb[q], v.y, h2[q][2 * p + 1]);
                }
            }
        }
    }

    // ---- folded enc3+proj: 32 -> 3, dot-form ----
    float x0[R], x1[R], x2[R];
    {
        ull ax0[R], ax1[R], ax2[R];
        {
            const ulonglong2* pb = reinterpret_cast<const ulonglong2*>(cP.Pbp);
            ulonglong2 v0 = pb[0];
            ull v2 = reinterpret_cast<const ull*>(cP.Pbp)[2];
#pragma unroll
            for (int q = 0; q < R; q++) { ax0[q] = v0.x; ax1[q] = v0.y; ax2[q] = v2; }
        }
        const ull* w0p = reinterpret_cast<const ull*>(cP.Wf);
        const ull* w1p = reinterpret_cast<const ull*>(cP.Wf + 32);
        const ull* w2p = reinterpret_cast<const ull*>(cP.Wf + 64);
#pragma unroll
        for (int j = 0; j < 16; j++) {
            ull w0 = w0p[j], w1 = w1p[j], w2 = w2p[j];
#pragma unroll
            for (int q = 0; q < R; q++) {
                ull h = relu2(h2[q][j]);
                ax0[q] = ffma2(h, w0, ax0[q]);
                ax1[q] = ffma2(h, w1, ax1[q]);
                ax2[q] = ffma2(h, w2, ax2[q]);
            }
        }
#pragma unroll
        for (int q = 0; q < R; q++) {
            x0[q] = hadd2(ax0[q]); x1[q] = hadd2(ax1[q]); x2[q] = hadd2(ax2[q]);
        }
    }

    // ---- MAF flow: 10 layers; output stage dot-form ----
#pragma unroll 1
    for (int l = 0; l < 10; l++) {
        const float* fhx0 = cP.FhX0 + l * 32;
        const float* fhx1 = cP.FhX1 + l * 16;
        const float* fbh  = cP.Fbh  + l * 32;
        const ull* fmu2   = reinterpret_cast<const ull*>(cP.FoMu2 + l * 32);
        const ull* fal2   = reinterpret_cast<const ull*>(cP.FoAl2 + l * 32);
        const ull* fmu1   = reinterpret_cast<const ull*>(cP.FoMu1 + l * 16);
        const ull* fal1   = reinterpret_cast<const ull*>(cP.FoAl1 + l * 16);
        const float* fba  = cP.FbA + l * 8;
        const float* fb0  = cP.Fb0 + l * 2;

        ull x0b[R], x1b[R];
#pragma unroll
        for (int q = 0; q < R; q++) { x0b[q] = pk2(x0[q], x0[q]); x1b[q] = pk2(x1[q], x1[q]); }

        ull am1[R], aa1[R], am2[R], aa2[R];
        {
            const ulonglong2* pb = reinterpret_cast<const ulonglong2*>(fba);
            ulonglong2 v0 = pb[0], v1 = pb[1];
#pragma unroll
            for (int q = 0; q < R; q++) { am1[q] = v0.x; aa1[q] = v0.y; am2[q] = v1.x; aa2[q] = v1.y; }
        }

        // ---- block1: 16 deg-2 units (x0 + x1 inputs; feed mu2/al2 only) ----
        {
            ull hh[R][8];
            const ulonglong2* pbh = reinterpret_cast<const ulonglong2*>(fbh);
#pragma unroll
            for (int p = 0; p < 4; p++) {
                ulonglong2 v = pbh[p];
#pragma unroll
                for (int q = 0; q < R; q++) { hh[q][2 * p] = v.x; hh[q][2 * p + 1] = v.y; }
            }
            const ulonglong2* w0 = reinterpret_cast<const ulonglong2*>(fhx0);
            const ulonglong2* w1 = reinterpret_cast<const ulonglong2*>(fhx1);
#pragma unroll
            for (int p = 0; p < 4; p++) {
                ulonglong2 v = w0[p];
#pragma unroll
                for (int q = 0; q < R; q++) {
                    hh[q][2 * p]     = ffma2(x0b[q], v.x, hh[q][2 * p]);
                    hh[q][2 * p + 1] = ffma2(x0b[q], v.y, hh[q][2 * p + 1]);
                }
            }
#pragma unroll
            for (int p = 0; p < 4; p++) {
                ulonglong2 v = w1[p];
#pragma unroll
                for (int q = 0; q < R; q++) {
                    hh[q][2 * p]     = ffma2(x1b[q], v.x, hh[q][2 * p]);
                    hh[q][2 * p + 1] = ffma2(x1b[q], v.y, hh[q][2 * p + 1]);
                }
            }
#pragma unroll
            for (int p = 0; p < 8; p++) {
                ull wm2 = fmu2[p], wa2 = fal2[p];
#pragma unroll
                for (int q = 0; q < R; q++) {
                    ull h = relu2(hh[q][p]);
                    am2[q] = ffma2(h, wm2, am2[q]);
                    aa2[q] = ffma2(h, wa2, aa2[q]);
                }
            }
        }
        // ---- block2: 16 deg-1 units (x0 only; feed mu1/al1 AND mu2/al2) ----
        {
            ull hh[R][8];
            const ulonglong2* pbh = reinterpret_cast<const ulonglong2*>(fbh + 16);
#pragma unroll
            for (int p = 0; p < 4; p++) {
                ulonglong2 v = pbh[p];
#pragma unroll
                for (int q = 0; q < R; q++) { hh[q][2 * p] = v.x; hh[q][2 * p + 1] = v.y; }
            }
            const ulonglong2* w0 = reinterpret_cast<const ulonglong2*>(fhx0 + 16);
#pragma unroll
            for (int p = 0; p < 4; p++) {
                ulonglong2 v = w0[p];
#pragma unroll
                for (int q = 0; q < R; q++) {
                    hh[q][2 * p]     = ffma2(x0b[q], v.x, hh[q][2 * p]);
                    hh[q][2 * p + 1] = ffma2(x0b[q], v.y, hh[q][2 * p + 1]);
                }
            }
#pragma unroll
            for (int p = 0; p < 8; p++) {
                ull wm2 = fmu2[8 + p], wa2 = fal2[8 + p];
                ull wm1 = fmu1[p],     wa1 = fal1[p];
#pragma unroll
                for (int q = 0; q < R; q++) {
                    ull h = relu2(hh[q][p]);
                    am2[q] = ffma2(h, wm2, am2[q]);
                    aa2[q] = ffma2(h, wa2, aa2[q]);
                    am1[q] = ffma2(h, wm1, am1[q]);
                    aa1[q] = ffma2(h, wa1, aa1[q]);
                }
            }
        }

        float bmu0 = fb0[0], esc0 = fb0[1];
#pragma unroll
        for (int q = 0; q < R; q++) {
            float mu1 = hadd2(am1[q]), al1 = hadd2(aa1[q]);
            float mu2 = hadd2(am2[q]), al2 = hadd2(aa2[q]);
            float t1 = tanh_fast(al1);
            float t2 = tanh_fast(al2);
            float nx0 = (x0[q] - bmu0) * esc0;
            float nx1 = (x1[q] - mu1) * __expf(-t1);
            float nx2 = (x2[q] - mu2) * __expf(-t2);
            x0[q] = nx2; x1[q] = nx1; x2[q] = nx0;
        }
    }

    // ---- squash + HSV + store  (sigmoid(x) = 0.5*(1+tanh(x/2))) ----
#pragma unroll
    for (int q = 0; q < R; q++) {
        int rq = rbase + q * 128;
        if (rq < B) {
            float t0 = tanh_fast(0.5f * x0[q]);
            float t1 = tanh_fast(0.5f * x1[q]);
            float t2 = tanh_fast(0.5f * x2[q]);
            out[3 * rq + 0] = fmaf(3.14159265358979323846f, t0, 3.14159265358979323846f);
            out[3 * rq + 1] = fmaf(0.5f, t1, 0.5f);
            out[3 * rq + 2] = fmaf(0.5f, t2, 0.5f);
        }
    }
}

extern "C" void kernel_launch(void* const* d_in, const int* in_sizes, int n_in,
                              void* d_out, int out_size) {
    (void)n_in; (void)out_size;
    const float* states   = (const float*)d_in[0];
    const float* enc_w1   = (const float*)d_in[1];
    const float* enc_b1   = (const float*)d_in[2];
    const float* enc_w2   = (const float*)d_in[3];
    const float* enc_b2   = (const float*)d_in[4];
    const float* enc_w3   = (const float*)d_in[5];
    const float* enc_b3   = (const float*)d_in[6];
    const float* proj_w   = (const float*)d_in[7];
    const float* proj_b   = (const float*)d_in[8];
    const float* flow_wh  = (const float*)d_in[9];
    const float* flow_bh  = (const float*)d_in[10];
    const float* flow_wmu = (const float*)d_in[11];
    const float* flow_bmu = (const float*)d_in[12];
    const float* flow_wa  = (const float*)d_in[13];
    const float* flow_ba  = (const float*)d_in[14];

    // 1) bake folded/permuted weights into device staging
    bake_kernel<<<1, 128>>>(enc_w1, enc_b1, enc_w2, enc_b2, enc_w3, enc_b3,
                            proj_w, proj_b, flow_wh, flow_bh, flow_wmu, flow_bmu,
                            flow_wa, flow_ba);
    // 2) staging -> __constant__ (D2D async; graph-capturable, no allocation)
    void* stage_ptr = nullptr;
    cudaGetSymbolAddress(&stage_ptr, g_stage);
    cudaMemcpyToSymbolAsync(cP, stage_ptr, sizeof(CParams), 0,
                            cudaMemcpyDeviceToDevice, 0);
    // 3) main kernel reads weights through the const/LDCU uniform path
    const int B = in_sizes[0] / 4;
    const int grid = (B + 128 * R - 1) / (128 * R);
    gsi_kernel<<<grid, 128>>>(states, (float*)d_out, B);
}